// round 5
// baseline (speedup 1.0000x reference)
#include <cuda_runtime.h>
#include <cuda_bf16.h>
#include <cuda_fp16.h>
#include <cstdint>

#define NN 50000
#define EE 800000
#define LRELU 0.2f
#define LN_EPS 1e-5f

// ------------------------- scratch (device globals) ----------------------
__device__ __align__(16) __half g_xs_h[(size_t)NN * 128];   // fp16 xs
__device__ float g_h[(size_t)NN * 128];                     // layer1 out
__device__ float g_acc1[(size_t)NN * 128];
__device__ float g_as[NN * 4];
__device__ float g_ad[NN * 4];
__device__ __align__(16) __half2 g_Wp[2 * 64 * 256];        // k2-paired weights [layer][k2][col]
__device__ float g_Vsd[2 * 128 * 8];                        // composite att vecs [layer][k][Vs0-3|Vd0-3]
__device__ float g_biasA[2 * 128];
// CSR
__device__ int g_cnt[NN];
__device__ int g_rowptr[NN + 1];
__device__ int g_woff[NN];
__device__ int g_csrc[EE];

// ------------------------- pack: weights->half2 pairs, V_s/V_d, bias -----
__global__ void pack_all(const float* __restrict__ W1s, const float* __restrict__ W1d,
                         const float* __restrict__ Wl1, const float* __restrict__ a1s,
                         const float* __restrict__ a1d, const float* __restrict__ bl1,
                         const float* __restrict__ b1,
                         const float* __restrict__ W2s, const float* __restrict__ W2d,
                         const float* __restrict__ Wl2, const float* __restrict__ a2s,
                         const float* __restrict__ a2d, const float* __restrict__ bl2,
                         const float* __restrict__ b2)
{
    int i = blockIdx.x * blockDim.x + threadIdx.x;
    // weight pack: cols [0,128)=W_src, [128,256)=W_lin ; half2 pairs along k
    if (i < 8192) {
        int k2 = i >> 7, c = i & 127;
        int k = k2 * 2;
        g_Wp[(size_t)k2 * 256 + c] =
            __floats2half2_rn(W1s[k * 128 + c], W1s[(k + 1) * 128 + c]);
        g_Wp[(size_t)k2 * 256 + 128 + c] =
            __floats2half2_rn(Wl1[k * 128 + c], Wl1[(k + 1) * 128 + c]);
        g_Wp[(size_t)(64 + k2) * 256 + c] =
            __floats2half2_rn(W2s[k * 128 + c], W2s[(k + 1) * 128 + c]);
        g_Wp[(size_t)(64 + k2) * 256 + 128 + c] =
            __floats2half2_rn(Wl2[k * 128 + c], Wl2[(k + 1) * 128 + c]);
    }
    // composite attention vectors: Vs[k][h] = sum_c W_src[k][h*32+c]*att_s[h][c]
    if (i < 2048) {
        int layer = i >> 10;
        int r = i & 1023;
        int k = r >> 3, col = r & 7;
        int h = col & 3, sd = col >> 2;
        const float* W = layer ? (sd ? W2d : W2s) : (sd ? W1d : W1s);
        const float* att = layer ? (sd ? a2d : a2s) : (sd ? a1d : a1s);
        float s = 0.f;
        #pragma unroll 8
        for (int c = 0; c < 32; c++)
            s = fmaf(W[k * 128 + h * 32 + c], att[h * 32 + c], s);
        g_Vsd[layer * 1024 + k * 8 + col] = s;
    }
    if (i < 128) {
        g_biasA[i]       = bl1[i] + b1[i];
        g_biasA[128 + i] = bl2[i] + b2[i];
    }
}

// ------------------------- CSR build -------------------------------------
__global__ void hist_k(const int* __restrict__ dst, int E)
{
    int e = blockIdx.x * blockDim.x + threadIdx.x;
    if (e < E) atomicAdd(&g_cnt[dst[e]], 1);
}

__global__ void scan_k(int E)
{
    __shared__ int ssum[1024];
    const int t = threadIdx.x;
    const int CH = (NN + 1023) / 1024;
    int base = t * CH;
    int s = 0;
    for (int i = 0; i < CH; i++) {
        int idx = base + i;
        if (idx < NN) s += g_cnt[idx];
    }
    ssum[t] = s;
    __syncthreads();
    for (int off = 1; off < 1024; off <<= 1) {
        int v = (t >= off) ? ssum[t - off] : 0;
        __syncthreads();
        ssum[t] += v;
        __syncthreads();
    }
    int run = ssum[t] - s;
    for (int i = 0; i < CH; i++) {
        int idx = base + i;
        if (idx < NN) {
            g_rowptr[idx] = run;
            g_woff[idx] = run;
            run += g_cnt[idx];
        }
    }
    if (t == 1023) g_rowptr[NN] = E;
}

__global__ void scatter_k(const int* __restrict__ src, const int* __restrict__ dst, int E)
{
    int e = blockIdx.x * blockDim.x + threadIdx.x;
    if (e >= E) return;
    int d = dst[e];
    int p = atomicAdd(&g_woff[d], 1);
    g_csrc[p] = src[e];
}

// ------------------------- fp16 tensor GEMM ------------------------------
// C[M,256] = fp16(A[M,128]) @ g_Wp; grid.y==0: xs cols -> fp16 g_xs_h
//                                   grid.y==1: lin cols + bias -> fp32 acc
__global__ __launch_bounds__(256) void gemm_h(const float* __restrict__ A,
                                              float* __restrict__ acc,
                                              const __half2* __restrict__ Wp,
                                              const float* __restrict__ biasv,
                                              int M)
{
    __shared__ __half2 As2[128][36];   // [row][k2], stride 36: frag bank = 4g+t4
    __shared__ __half2 Bs2[32][136];   // [k2][col], stride 136: frag bank = 8t4+g

    const int tid = threadIdx.x;
    const int lane = tid & 31;
    const int warp = tid >> 5;
    const int wm = warp >> 2;
    const int wn = warp & 3;
    const int row0 = blockIdx.x * 128;
    const int y = blockIdx.y;
    const int col0 = y * 128;
    const int g = lane >> 2;
    const int t4 = lane & 3;

    float c[4][4][4];
    #pragma unroll
    for (int i = 0; i < 4; i++)
        #pragma unroll
        for (int j = 0; j < 4; j++)
            #pragma unroll
            for (int q = 0; q < 4; q++) c[i][j][q] = 0.f;

    for (int k0 = 0; k0 < 128; k0 += 64) {
        // A tile: 128 rows x 64 k (fp32 -> half2 pairs along k)
        {
            int ar = tid >> 1;
            int ah = tid & 1;
            int grow = row0 + ar;
            #pragma unroll
            for (int j = 0; j < 8; j++) {
                float4 v = make_float4(0.f, 0.f, 0.f, 0.f);
                if (grow < M)
                    v = *(const float4*)(A + (size_t)grow * 128 + k0 + ah * 32 + j * 4);
                As2[ar][ah * 16 + j * 2]     = __floats2half2_rn(v.x, v.y);
                As2[ar][ah * 16 + j * 2 + 1] = __floats2half2_rn(v.z, v.w);
            }
        }
        // B tile: 32 k2 x 128 cols (pre-paired half2, straight copy)
        {
            int k2r = tid >> 3;
            int colg = (tid & 7) * 16;
            const uint4* srcp = (const uint4*)(Wp + (size_t)(k0 / 2 + k2r) * 256 + col0 + colg);
            #pragma unroll
            for (int q = 0; q < 4; q++)
                *(uint4*)&Bs2[k2r][colg + q * 4] = srcp[q];
        }
        __syncthreads();

        #pragma unroll
        for (int kk = 0; kk < 4; kk++) {
            uint32_t af[4][4], bf[4][2];
            #pragma unroll
            for (int mt = 0; mt < 4; mt++) {
                int r = wm * 64 + mt * 16 + g;
                af[mt][0] = *(const uint32_t*)&As2[r][kk * 8 + t4];
                af[mt][1] = *(const uint32_t*)&As2[r + 8][kk * 8 + t4];
                af[mt][2] = *(const uint32_t*)&As2[r][kk * 8 + 4 + t4];
                af[mt][3] = *(const uint32_t*)&As2[r + 8][kk * 8 + 4 + t4];
            }
            #pragma unroll
            for (int nt = 0; nt < 4; nt++) {
                int cc = wn * 32 + nt * 8 + g;
                bf[nt][0] = *(const uint32_t*)&Bs2[kk * 8 + t4][cc];
                bf[nt][1] = *(const uint32_t*)&Bs2[kk * 8 + 4 + t4][cc];
            }
            #pragma unroll
            for (int mt = 0; mt < 4; mt++)
                #pragma unroll
                for (int nt = 0; nt < 4; nt++) {
                    asm volatile(
                        "mma.sync.aligned.m16n8k16.row.col.f32.f16.f16.f32 "
                        "{%0,%1,%2,%3}, {%4,%5,%6,%7}, {%8,%9}, {%0,%1,%2,%3};"
                        : "+f"(c[mt][nt][0]), "+f"(c[mt][nt][1]),
                          "+f"(c[mt][nt][2]), "+f"(c[mt][nt][3])
                        : "r"(af[mt][0]), "r"(af[mt][1]), "r"(af[mt][2]), "r"(af[mt][3]),
                          "r"(bf[nt][0]), "r"(bf[nt][1]));
                }
        }
        __syncthreads();
    }

    const int l2 = t4 * 2;
    if (y == 0) {
        #pragma unroll
        for (int mt = 0; mt < 4; mt++) {
            #pragma unroll
            for (int nt = 0; nt < 4; nt++) {
                int r = row0 + wm * 64 + mt * 16 + g;
                int cc = wn * 32 + nt * 8 + l2;
                if (r < M)
                    *(half2*)(g_xs_h + (size_t)r * 128 + cc) =
                        __floats2half2_rn(c[mt][nt][0], c[mt][nt][1]);
                if (r + 8 < M)
                    *(half2*)(g_xs_h + (size_t)(r + 8) * 128 + cc) =
                        __floats2half2_rn(c[mt][nt][2], c[mt][nt][3]);
            }
        }
    } else {
        #pragma unroll
        for (int mt = 0; mt < 4; mt++) {
            #pragma unroll
            for (int nt = 0; nt < 4; nt++) {
                int r = row0 + wm * 64 + mt * 16 + g;
                int cc = wn * 32 + nt * 8 + l2;
                float2 b2 = *(const float2*)(biasv + cc);
                float2 v01 = make_float2(c[mt][nt][0] + b2.x, c[mt][nt][1] + b2.y);
                float2 v23 = make_float2(c[mt][nt][2] + b2.x, c[mt][nt][3] + b2.y);
                if (r < M)     *(float2*)(acc + (size_t)r * 128 + cc) = v01;
                if (r + 8 < M) *(float2*)(acc + (size_t)(r + 8) * 128 + cc) = v23;
            }
        }
    }
}

// ------------------------- node logits: [a_s|a_d] = X @ Vsd[128,8] -------
__global__ __launch_bounds__(256) void node_logits(const float* __restrict__ X,
                                                   const float* __restrict__ Vsd, int n)
{
    const int lane = threadIdx.x & 31;
    int gw = (blockIdx.x * blockDim.x + threadIdx.x) >> 5;
    const int nwarps = (gridDim.x * blockDim.x) >> 5;

    float4 va[4], vb[4];
    #pragma unroll
    for (int j = 0; j < 4; j++) {
        va[j] = *(const float4*)(Vsd + (lane * 4 + j) * 8);
        vb[j] = *(const float4*)(Vsd + (lane * 4 + j) * 8 + 4);
    }

    for (int node = gw; node < n; node += nwarps) {
        float4 xv = *(const float4*)(X + (size_t)node * 128 + lane * 4);
        float4 s, d;
        s.x = xv.x * va[0].x + xv.y * va[1].x + xv.z * va[2].x + xv.w * va[3].x;
        s.y = xv.x * va[0].y + xv.y * va[1].y + xv.z * va[2].y + xv.w * va[3].y;
        s.z = xv.x * va[0].z + xv.y * va[1].z + xv.z * va[2].z + xv.w * va[3].z;
        s.w = xv.x * va[0].w + xv.y * va[1].w + xv.z * va[2].w + xv.w * va[3].w;
        d.x = xv.x * vb[0].x + xv.y * vb[1].x + xv.z * vb[2].x + xv.w * vb[3].x;
        d.y = xv.x * vb[0].y + xv.y * vb[1].y + xv.z * vb[2].y + xv.w * vb[3].y;
        d.z = xv.x * vb[0].z + xv.y * vb[1].z + xv.z * vb[2].z + xv.w * vb[3].z;
        d.w = xv.x * vb[0].w + xv.y * vb[1].w + xv.z * vb[2].w + xv.w * vb[3].w;
        #pragma unroll
        for (int m = 16; m >= 1; m >>= 1) {
            s.x += __shfl_xor_sync(0xFFFFFFFFu, s.x, m);
            s.y += __shfl_xor_sync(0xFFFFFFFFu, s.y, m);
            s.z += __shfl_xor_sync(0xFFFFFFFFu, s.z, m);
            s.w += __shfl_xor_sync(0xFFFFFFFFu, s.w, m);
            d.x += __shfl_xor_sync(0xFFFFFFFFu, d.x, m);
            d.y += __shfl_xor_sync(0xFFFFFFFFu, d.y, m);
            d.z += __shfl_xor_sync(0xFFFFFFFFu, d.z, m);
            d.w += __shfl_xor_sync(0xFFFFFFFFu, d.w, m);
        }
        if (lane == 0) {
            *(float4*)(g_as + (size_t)node * 4) = s;
            *(float4*)(g_ad + (size_t)node * 4) = d;
        }
    }
}

// ------------------------- fast exp (FMA pipe, no MUFU) ------------------
__device__ __forceinline__ float fast_exp(float x)
{
    float t  = fmaf(x, 1.4426950408889634f, 12582912.0f);
    int   i  = __float_as_int(t);
    float fi = t - 12582912.0f;
    float f  = fmaf(x, 1.4426950408889634f, -fi);   // in [-0.5, 0.5]
    float p  = 0.0013333558f;
    p = fmaf(p, f, 0.0096181291f);
    p = fmaf(p, f, 0.0555041087f);
    p = fmaf(p, f, 0.2402265070f);
    p = fmaf(p, f, 0.6931471806f);
    p = fmaf(p, f, 1.0f);
    return __int_as_float(__float_as_int(p) + (i << 23));
}

// ------------------------- fused edge softmax-SpMM (+LN) -----------------
// out[node] = (sum_e w_e * xs[src_e]) / (sum_e w_e);  single pass, no g_w.
template <bool DO_LN>
__global__ __launch_bounds__(256) void edge_fused(float* __restrict__ io,
                                                  const float* __restrict__ gamma,
                                                  const float* __restrict__ beta,
                                                  int n)
{
    int node = (blockIdx.x * blockDim.x + threadIdx.x) >> 5;
    int lane = threadIdx.x & 31;
    if (node >= n) return;
    const int h = lane >> 3;
    const int rs = g_rowptr[node], re = g_rowptr[node + 1];
    const float adh = g_ad[(size_t)node * 4 + h];

    float4 a = make_float4(0.f, 0.f, 0.f, 0.f);
    float den = 0.f;
    #pragma unroll 4
    for (int e = rs; e < re; e++) {
        int s = g_csrc[e];
        float v = g_as[(size_t)s * 4 + h] + adh;
        v = v > 0.f ? v : LRELU * v;
        float w = fast_exp(v);
        den += w;
        uint2 raw = *(const uint2*)(g_xs_h + (size_t)s * 128 + lane * 4);
        float2 lo = __half22float2(*(half2*)&raw.x);
        float2 hi = __half22float2(*(half2*)&raw.y);
        a.x = fmaf(w, lo.x, a.x);
        a.y = fmaf(w, lo.y, a.y);
        a.z = fmaf(w, hi.x, a.z);
        a.w = fmaf(w, hi.y, a.w);
    }
    const float inv = __fdividef(1.f, den + 1e-16f);

    float4 o = *(const float4*)(io + (size_t)node * 128 + lane * 4);
    o.x = fmaf(a.x, inv, o.x);
    o.y = fmaf(a.y, inv, o.y);
    o.z = fmaf(a.z, inv, o.z);
    o.w = fmaf(a.w, inv, o.w);

    if (DO_LN) {
        float sum = o.x + o.y + o.z + o.w;
        float sq  = o.x * o.x + o.y * o.y + o.z * o.z + o.w * o.w;
        #pragma unroll
        for (int m = 1; m <= 16; m <<= 1) {
            sum += __shfl_xor_sync(0xFFFFFFFFu, sum, m);
            sq  += __shfl_xor_sync(0xFFFFFFFFu, sq, m);
        }
        float mean = sum * (1.f / 128.f);
        float var  = sq * (1.f / 128.f) - mean * mean;
        float rstd = rsqrtf(var + LN_EPS);
        float4 g4 = *(const float4*)(gamma + lane * 4);
        float4 b4 = *(const float4*)(beta + lane * 4);
        float4 r;
        r.x = fmaxf(0.f, (o.x - mean) * rstd * g4.x + b4.x);
        r.y = fmaxf(0.f, (o.y - mean) * rstd * g4.y + b4.y);
        r.z = fmaxf(0.f, (o.z - mean) * rstd * g4.z + b4.z);
        r.w = fmaxf(0.f, (o.w - mean) * rstd * g4.w + b4.w);
        *(float4*)(g_h + (size_t)node * 128 + lane * 4) = r;
    } else {
        *(float4*)(io + (size_t)node * 128 + lane * 4) = o;
    }
}

// ------------------------- driver ----------------------------------------
extern "C" void kernel_launch(void* const* d_in, const int* in_sizes, int n_in,
                              void* d_out, int out_size)
{
    const float* x        = (const float*)d_in[0];
    const int*   ei       = (const int*)  d_in[1];
    const float* W1_src   = (const float*)d_in[2];
    const float* W1_dst   = (const float*)d_in[3];
    const float* att1_src = (const float*)d_in[4];
    const float* att1_dst = (const float*)d_in[5];
    const float* b1       = (const float*)d_in[6];
    const float* Wl1      = (const float*)d_in[7];
    const float* bl1      = (const float*)d_in[8];
    const float* gamma    = (const float*)d_in[9];
    const float* beta     = (const float*)d_in[10];
    const float* W2_src   = (const float*)d_in[11];
    const float* W2_dst   = (const float*)d_in[12];
    const float* att2_src = (const float*)d_in[13];
    const float* att2_dst = (const float*)d_in[14];
    const float* b2       = (const float*)d_in[15];
    const float* Wl2      = (const float*)d_in[16];
    const float* bl2      = (const float*)d_in[17];
    float* out = (float*)d_out;

    const int n = NN;
    const int E = EE;
    const int* src = ei;
    const int* dst = ei + E;

    void* p;
    cudaGetSymbolAddress(&p, g_acc1);  float* acc1 = (float*)p;
    cudaGetSymbolAddress(&p, g_h);     float* hbuf = (float*)p;
    cudaGetSymbolAddress(&p, g_Wp);    __half2* wp = (__half2*)p;
    cudaGetSymbolAddress(&p, g_biasA); float* bias = (float*)p;
    cudaGetSymbolAddress(&p, g_Vsd);   float* vsd  = (float*)p;
    void* cntp;
    cudaGetSymbolAddress(&cntp, g_cnt);

    dim3 gemm_grid((n + 127) / 128, 2);
    int node_blocks = (n * 32 + 255) / 256;
    int edge_blocks = (E + 255) / 256;

    // CSR build (reused by both layers)
    cudaMemsetAsync(cntp, 0, NN * sizeof(int));
    hist_k<<<edge_blocks, 256>>>(dst, E);
    scan_k<<<1, 1024>>>(E);
    scatter_k<<<edge_blocks, 256>>>(src, dst, E);

    pack_all<<<64, 256>>>(W1_src, W1_dst, Wl1, att1_src, att1_dst, bl1, b1,
                          W2_src, W2_dst, Wl2, att2_src, att2_dst, bl2, b2);

    // layer 1
    node_logits<<<512, 256>>>(x, vsd, n);
    gemm_h<<<gemm_grid, 256>>>(x, acc1, wp, bias, n);
    edge_fused<true><<<node_blocks, 256>>>(acc1, gamma, beta, n);

    // layer 2
    node_logits<<<512, 256>>>(hbuf, vsd + 1024, n);
    gemm_h<<<gemm_grid, 256>>>(hbuf, out, wp + 64 * 256, bias + 128, n);
    edge_fused<false><<<node_blocks, 256>>>(out, nullptr, nullptr, n);
}

// round 6
// speedup vs baseline: 1.0492x; 1.0492x over previous
#include <cuda_runtime.h>
#include <cuda_bf16.h>
#include <cuda_fp16.h>
#include <cstdint>

#define NN 50000
#define EE 800000
#define LRELU 0.2f
#define LN_EPS 1e-5f

// ------------------------- scratch (device globals) ----------------------
__device__ __align__(16) __half g_xs_h[(size_t)NN * 128];   // fp16 xs
__device__ float g_h[(size_t)NN * 128];                     // layer1 out
__device__ float g_acc1[(size_t)NN * 128];
__device__ float g_as[NN * 4];
__device__ float g_ad[NN * 4];
__device__ __align__(16) __half2 g_Wp[2 * 64 * 256];        // k2-paired weights
__device__ float g_Vsd[2 * 128 * 8];                        // [layer][k][Vs0-3|Vd0-3]
__device__ float g_biasA[2 * 128];
// CSR
__device__ int g_cnt[NN];
__device__ int g_rowptr[NN + 1];
__device__ int g_woff[NN];
__device__ int g_csrc[EE];

// ------------------------- pack: weights->half2, V_s/V_d (warp-par) ------
__global__ void pack_all(const float* __restrict__ W1s, const float* __restrict__ W1d,
                         const float* __restrict__ Wl1, const float* __restrict__ a1s,
                         const float* __restrict__ a1d, const float* __restrict__ bl1,
                         const float* __restrict__ b1,
                         const float* __restrict__ W2s, const float* __restrict__ W2d,
                         const float* __restrict__ Wl2, const float* __restrict__ a2s,
                         const float* __restrict__ a2d, const float* __restrict__ bl2,
                         const float* __restrict__ b2)
{
    int i = blockIdx.x * blockDim.x + threadIdx.x;   // 65536 threads
    if (i < 8192) {
        int k2 = i >> 7, c = i & 127;
        int k = k2 * 2;
        g_Wp[(size_t)k2 * 256 + c] =
            __floats2half2_rn(W1s[k * 128 + c], W1s[(k + 1) * 128 + c]);
        g_Wp[(size_t)k2 * 256 + 128 + c] =
            __floats2half2_rn(Wl1[k * 128 + c], Wl1[(k + 1) * 128 + c]);
        g_Wp[(size_t)(64 + k2) * 256 + c] =
            __floats2half2_rn(W2s[k * 128 + c], W2s[(k + 1) * 128 + c]);
        g_Wp[(size_t)(64 + k2) * 256 + 128 + c] =
            __floats2half2_rn(Wl2[k * 128 + c], Wl2[(k + 1) * 128 + c]);
    }
    // Vsd: one warp per output element, lanes over c
    {
        int w = i >> 5;                 // 0..2047
        int lane = i & 31;
        int layer = w >> 10;
        int r = w & 1023;
        int k = r >> 3, col = r & 7;
        int h = col & 3, sd = col >> 2;
        const float* W = layer ? (sd ? W2d : W2s) : (sd ? W1d : W1s);
        const float* att = layer ? (sd ? a2d : a2s) : (sd ? a1d : a1s);
        float s = W[k * 128 + h * 32 + lane] * att[h * 32 + lane];
        #pragma unroll
        for (int m = 16; m >= 1; m >>= 1)
            s += __shfl_xor_sync(0xFFFFFFFFu, s, m);
        if (lane == 0) g_Vsd[layer * 1024 + k * 8 + col] = s;
    }
    if (i < 128) {
        g_biasA[i]       = bl1[i] + b1[i];
        g_biasA[128 + i] = bl2[i] + b2[i];
    }
}

// ------------------------- CSR build -------------------------------------
__global__ void hist_k(const int* __restrict__ dst, int E)
{
    int e = blockIdx.x * blockDim.x + threadIdx.x;
    if (e < E) atomicAdd(&g_cnt[dst[e]], 1);
}

__global__ void scan_k(int E)
{
    __shared__ int ssum[1024];
    const int t = threadIdx.x;
    const int CH = (NN + 1023) / 1024;
    int base = t * CH;
    int s = 0;
    for (int i = 0; i < CH; i++) {
        int idx = base + i;
        if (idx < NN) s += g_cnt[idx];
    }
    ssum[t] = s;
    __syncthreads();
    for (int off = 1; off < 1024; off <<= 1) {
        int v = (t >= off) ? ssum[t - off] : 0;
        __syncthreads();
        ssum[t] += v;
        __syncthreads();
    }
    int run = ssum[t] - s;
    for (int i = 0; i < CH; i++) {
        int idx = base + i;
        if (idx < NN) {
            g_rowptr[idx] = run;
            g_woff[idx] = run;
            run += g_cnt[idx];
        }
    }
    if (t == 1023) g_rowptr[NN] = E;
}

__global__ void scatter_k(const int* __restrict__ src, const int* __restrict__ dst, int E)
{
    int e = blockIdx.x * blockDim.x + threadIdx.x;
    if (e >= E) return;
    int d = dst[e];
    int p = atomicAdd(&g_woff[d], 1);
    g_csrc[p] = src[e];
}

// ------------------------- fp16 tensor GEMM (unchanged, passing) ---------
__global__ __launch_bounds__(256) void gemm_h(const float* __restrict__ A,
                                              float* __restrict__ acc,
                                              const __half2* __restrict__ Wp,
                                              const float* __restrict__ biasv,
                                              int M)
{
    __shared__ __half2 As2[128][36];
    __shared__ __half2 Bs2[32][136];

    const int tid = threadIdx.x;
    const int lane = tid & 31;
    const int warp = tid >> 5;
    const int wm = warp >> 2;
    const int wn = warp & 3;
    const int row0 = blockIdx.x * 128;
    const int y = blockIdx.y;
    const int col0 = y * 128;
    const int g = lane >> 2;
    const int t4 = lane & 3;

    float c[4][4][4];
    #pragma unroll
    for (int i = 0; i < 4; i++)
        #pragma unroll
        for (int j = 0; j < 4; j++)
            #pragma unroll
            for (int q = 0; q < 4; q++) c[i][j][q] = 0.f;

    for (int k0 = 0; k0 < 128; k0 += 64) {
        {
            int ar = tid >> 1;
            int ah = tid & 1;
            int grow = row0 + ar;
            #pragma unroll
            for (int j = 0; j < 8; j++) {
                float4 v = make_float4(0.f, 0.f, 0.f, 0.f);
                if (grow < M)
                    v = *(const float4*)(A + (size_t)grow * 128 + k0 + ah * 32 + j * 4);
                As2[ar][ah * 16 + j * 2]     = __floats2half2_rn(v.x, v.y);
                As2[ar][ah * 16 + j * 2 + 1] = __floats2half2_rn(v.z, v.w);
            }
        }
        {
            int k2r = tid >> 3;
            int colg = (tid & 7) * 16;
            const uint4* srcp = (const uint4*)(Wp + (size_t)(k0 / 2 + k2r) * 256 + col0 + colg);
            #pragma unroll
            for (int q = 0; q < 4; q++)
                *(uint4*)&Bs2[k2r][colg + q * 4] = srcp[q];
        }
        __syncthreads();

        #pragma unroll
        for (int kk = 0; kk < 4; kk++) {
            uint32_t af[4][4], bf[4][2];
            #pragma unroll
            for (int mt = 0; mt < 4; mt++) {
                int r = wm * 64 + mt * 16 + g;
                af[mt][0] = *(const uint32_t*)&As2[r][kk * 8 + t4];
                af[mt][1] = *(const uint32_t*)&As2[r + 8][kk * 8 + t4];
                af[mt][2] = *(const uint32_t*)&As2[r][kk * 8 + 4 + t4];
                af[mt][3] = *(const uint32_t*)&As2[r + 8][kk * 8 + 4 + t4];
            }
            #pragma unroll
            for (int nt = 0; nt < 4; nt++) {
                int cc = wn * 32 + nt * 8 + g;
                bf[nt][0] = *(const uint32_t*)&Bs2[kk * 8 + t4][cc];
                bf[nt][1] = *(const uint32_t*)&Bs2[kk * 8 + 4 + t4][cc];
            }
            #pragma unroll
            for (int mt = 0; mt < 4; mt++)
                #pragma unroll
                for (int nt = 0; nt < 4; nt++) {
                    asm volatile(
                        "mma.sync.aligned.m16n8k16.row.col.f32.f16.f16.f32 "
                        "{%0,%1,%2,%3}, {%4,%5,%6,%7}, {%8,%9}, {%0,%1,%2,%3};"
                        : "+f"(c[mt][nt][0]), "+f"(c[mt][nt][1]),
                          "+f"(c[mt][nt][2]), "+f"(c[mt][nt][3])
                        : "r"(af[mt][0]), "r"(af[mt][1]), "r"(af[mt][2]), "r"(af[mt][3]),
                          "r"(bf[nt][0]), "r"(bf[nt][1]));
                }
        }
        __syncthreads();
    }

    const int l2 = t4 * 2;
    if (y == 0) {
        #pragma unroll
        for (int mt = 0; mt < 4; mt++) {
            #pragma unroll
            for (int nt = 0; nt < 4; nt++) {
                int r = row0 + wm * 64 + mt * 16 + g;
                int cc = wn * 32 + nt * 8 + l2;
                if (r < M)
                    *(half2*)(g_xs_h + (size_t)r * 128 + cc) =
                        __floats2half2_rn(c[mt][nt][0], c[mt][nt][1]);
                if (r + 8 < M)
                    *(half2*)(g_xs_h + (size_t)(r + 8) * 128 + cc) =
                        __floats2half2_rn(c[mt][nt][2], c[mt][nt][3]);
            }
        }
    } else {
        #pragma unroll
        for (int mt = 0; mt < 4; mt++) {
            #pragma unroll
            for (int nt = 0; nt < 4; nt++) {
                int r = row0 + wm * 64 + mt * 16 + g;
                int cc = wn * 32 + nt * 8 + l2;
                float2 b2 = *(const float2*)(biasv + cc);
                float2 v01 = make_float2(c[mt][nt][0] + b2.x, c[mt][nt][1] + b2.y);
                float2 v23 = make_float2(c[mt][nt][2] + b2.x, c[mt][nt][3] + b2.y);
                if (r < M)     *(float2*)(acc + (size_t)r * 128 + cc) = v01;
                if (r + 8 < M) *(float2*)(acc + (size_t)(r + 8) * 128 + cc) = v23;
            }
        }
    }
}

// ------------------------- node logits -----------------------------------
__global__ __launch_bounds__(256) void node_logits(const float* __restrict__ X,
                                                   const float* __restrict__ Vsd, int n)
{
    const int lane = threadIdx.x & 31;
    int gw = (blockIdx.x * blockDim.x + threadIdx.x) >> 5;
    const int nwarps = (gridDim.x * blockDim.x) >> 5;

    float4 va[4], vb[4];
    #pragma unroll
    for (int j = 0; j < 4; j++) {
        va[j] = *(const float4*)(Vsd + (lane * 4 + j) * 8);
        vb[j] = *(const float4*)(Vsd + (lane * 4 + j) * 8 + 4);
    }

    for (int node = gw; node < n; node += nwarps) {
        float4 xv = *(const float4*)(X + (size_t)node * 128 + lane * 4);
        float4 s, d;
        s.x = xv.x * va[0].x + xv.y * va[1].x + xv.z * va[2].x + xv.w * va[3].x;
        s.y = xv.x * va[0].y + xv.y * va[1].y + xv.z * va[2].y + xv.w * va[3].y;
        s.z = xv.x * va[0].z + xv.y * va[1].z + xv.z * va[2].z + xv.w * va[3].z;
        s.w = xv.x * va[0].w + xv.y * va[1].w + xv.z * va[2].w + xv.w * va[3].w;
        d.x = xv.x * vb[0].x + xv.y * vb[1].x + xv.z * vb[2].x + xv.w * vb[3].x;
        d.y = xv.x * vb[0].y + xv.y * vb[1].y + xv.z * vb[2].y + xv.w * vb[3].y;
        d.z = xv.x * vb[0].z + xv.y * vb[1].z + xv.z * vb[2].z + xv.w * vb[3].z;
        d.w = xv.x * vb[0].w + xv.y * vb[1].w + xv.z * vb[2].w + xv.w * vb[3].w;
        #pragma unroll
        for (int m = 16; m >= 1; m >>= 1) {
            s.x += __shfl_xor_sync(0xFFFFFFFFu, s.x, m);
            s.y += __shfl_xor_sync(0xFFFFFFFFu, s.y, m);
            s.z += __shfl_xor_sync(0xFFFFFFFFu, s.z, m);
            s.w += __shfl_xor_sync(0xFFFFFFFFu, s.w, m);
            d.x += __shfl_xor_sync(0xFFFFFFFFu, d.x, m);
            d.y += __shfl_xor_sync(0xFFFFFFFFu, d.y, m);
            d.z += __shfl_xor_sync(0xFFFFFFFFu, d.z, m);
            d.w += __shfl_xor_sync(0xFFFFFFFFu, d.w, m);
        }
        if (lane == 0) {
            *(float4*)(g_as + (size_t)node * 4) = s;
            *(float4*)(g_ad + (size_t)node * 4) = d;
        }
    }
}

// ------------------------- fast exp (FMA pipe) ---------------------------
__device__ __forceinline__ float fast_exp(float x)
{
    float t  = fmaf(x, 1.4426950408889634f, 12582912.0f);
    int   i  = __float_as_int(t);
    float fi = t - 12582912.0f;
    float f  = fmaf(x, 1.4426950408889634f, -fi);
    float p  = 0.0013333558f;
    p = fmaf(p, f, 0.0096181291f);
    p = fmaf(p, f, 0.0555041087f);
    p = fmaf(p, f, 0.2402265070f);
    p = fmaf(p, f, 0.6931471806f);
    p = fmaf(p, f, 1.0f);
    return __int_as_float(__float_as_int(p) + (i << 23));
}

// ------------------------- fused edge softmax-SpMM (+LN) -----------------
// chunk-of-32 lane-parallel weights, then 2-edges/iter LDG.128 gather.
template <bool DO_LN>
__global__ __launch_bounds__(256) void edge_fused(float* __restrict__ io,
                                                  const float* __restrict__ gamma,
                                                  const float* __restrict__ beta,
                                                  int n)
{
    __shared__ float4 s_w4[8][32];     // [warp][edge-in-chunk]
    const int wid = threadIdx.x >> 5;
    const int lane = threadIdx.x & 31;
    int node = (blockIdx.x * blockDim.x + threadIdx.x) >> 5;
    if (node >= n) return;

    const int rs = g_rowptr[node], re = g_rowptr[node + 1];
    const float4 ad4 = *(const float4*)(g_ad + (size_t)node * 4);
    const int hh = (lane & 15) >> 2;           // head of my 8 features
    const int feat = (lane & 15) * 8;          // my 8 features

    float acc[8] = {0.f, 0.f, 0.f, 0.f, 0.f, 0.f, 0.f, 0.f};
    float4 den = make_float4(0.f, 0.f, 0.f, 0.f);

    for (int base = rs; base < re; base += 32) {
        // phase 1: lane-parallel edge weights for this chunk
        int e = base + lane;
        int sreg = 0;
        float4 w4 = make_float4(0.f, 0.f, 0.f, 0.f);
        if (e < re) {
            sreg = g_csrc[e];
            float4 a = *(const float4*)(g_as + (size_t)sreg * 4);
            float vx = a.x + ad4.x, vy = a.y + ad4.y;
            float vz = a.z + ad4.z, vw = a.w + ad4.w;
            vx = vx > 0.f ? vx : LRELU * vx;
            vy = vy > 0.f ? vy : LRELU * vy;
            vz = vz > 0.f ? vz : LRELU * vz;
            vw = vw > 0.f ? vw : LRELU * vw;
            w4.x = fast_exp(vx); w4.y = fast_exp(vy);
            w4.z = fast_exp(vz); w4.w = fast_exp(vw);
        }
        float4 t = w4;
        #pragma unroll
        for (int m = 16; m >= 1; m >>= 1) {
            t.x += __shfl_xor_sync(0xFFFFFFFFu, t.x, m);
            t.y += __shfl_xor_sync(0xFFFFFFFFu, t.y, m);
            t.z += __shfl_xor_sync(0xFFFFFFFFu, t.z, m);
            t.w += __shfl_xor_sync(0xFFFFFFFFu, t.w, m);
        }
        den.x += t.x; den.y += t.y; den.z += t.z; den.w += t.w;
        s_w4[wid][lane] = w4;
        __syncwarp();

        // phase 2: gather, 2 edges per iteration (half-warp each, LDG.128)
        int cnt = min(32, re - base);
        int iters = (cnt + 1) >> 1;
        #pragma unroll 4
        for (int it = 0; it < iters; it++) {
            int jsel = 2 * it + (lane >> 4);
            int sj = __shfl_sync(0xFFFFFFFFu, sreg, jsel);
            float wv = ((const float*)&s_w4[wid][jsel])[hh];   // 0 for padding
            uint4 raw = *(const uint4*)(g_xs_h + (size_t)sj * 128 + feat);
            float2 f0 = __half22float2(*(half2*)&raw.x);
            float2 f1 = __half22float2(*(half2*)&raw.y);
            float2 f2 = __half22float2(*(half2*)&raw.z);
            float2 f3 = __half22float2(*(half2*)&raw.w);
            acc[0] = fmaf(wv, f0.x, acc[0]); acc[1] = fmaf(wv, f0.y, acc[1]);
            acc[2] = fmaf(wv, f1.x, acc[2]); acc[3] = fmaf(wv, f1.y, acc[3]);
            acc[4] = fmaf(wv, f2.x, acc[4]); acc[5] = fmaf(wv, f2.y, acc[5]);
            acc[6] = fmaf(wv, f3.x, acc[6]); acc[7] = fmaf(wv, f3.y, acc[7]);
        }
        __syncwarp();
    }

    // combine the two half-warps (lane l and l+16 hold same features)
    #pragma unroll
    for (int k = 0; k < 8; k++)
        acc[k] += __shfl_xor_sync(0xFFFFFFFFu, acc[k], 16);

    float dh = (hh < 2) ? (hh == 0 ? den.x : den.y) : (hh == 2 ? den.z : den.w);
    float inv = __fdividef(1.f, dh + 1e-16f);

    float4 i0 = *(const float4*)(io + (size_t)node * 128 + feat);
    float4 i1 = *(const float4*)(io + (size_t)node * 128 + feat + 4);
    float o[8];
    o[0] = fmaf(acc[0], inv, i0.x); o[1] = fmaf(acc[1], inv, i0.y);
    o[2] = fmaf(acc[2], inv, i0.z); o[3] = fmaf(acc[3], inv, i0.w);
    o[4] = fmaf(acc[4], inv, i1.x); o[5] = fmaf(acc[5], inv, i1.y);
    o[6] = fmaf(acc[6], inv, i1.z); o[7] = fmaf(acc[7], inv, i1.w);

    if (DO_LN) {
        float sum = 0.f, sq = 0.f;
        #pragma unroll
        for (int k = 0; k < 8; k++) { sum += o[k]; sq = fmaf(o[k], o[k], sq); }
        #pragma unroll
        for (int m = 1; m <= 16; m <<= 1) {
            sum += __shfl_xor_sync(0xFFFFFFFFu, sum, m);
            sq  += __shfl_xor_sync(0xFFFFFFFFu, sq, m);
        }
        // lanes duplicated x2 -> divide by 256
        float mean = sum * (1.f / 256.f);
        float var  = sq * (1.f / 256.f) - mean * mean;
        float rstd = rsqrtf(var + LN_EPS);
        float4 ga = *(const float4*)(gamma + feat);
        float4 gb = *(const float4*)(gamma + feat + 4);
        float4 ba = *(const float4*)(beta + feat);
        float4 bb = *(const float4*)(beta + feat + 4);
        float r[8];
        r[0] = fmaxf(0.f, (o[0] - mean) * rstd * ga.x + ba.x);
        r[1] = fmaxf(0.f, (o[1] - mean) * rstd * ga.y + ba.y);
        r[2] = fmaxf(0.f, (o[2] - mean) * rstd * ga.z + ba.z);
        r[3] = fmaxf(0.f, (o[3] - mean) * rstd * ga.w + ba.w);
        r[4] = fmaxf(0.f, (o[4] - mean) * rstd * gb.x + bb.x);
        r[5] = fmaxf(0.f, (o[5] - mean) * rstd * gb.y + bb.y);
        r[6] = fmaxf(0.f, (o[6] - mean) * rstd * gb.z + bb.z);
        r[7] = fmaxf(0.f, (o[7] - mean) * rstd * gb.w + bb.w);
        if (lane < 16) {
            *(float4*)(g_h + (size_t)node * 128 + feat)     = make_float4(r[0], r[1], r[2], r[3]);
            *(float4*)(g_h + (size_t)node * 128 + feat + 4) = make_float4(r[4], r[5], r[6], r[7]);
        }
    } else {
        if (lane < 16) {
            *(float4*)(io + (size_t)node * 128 + feat)     = make_float4(o[0], o[1], o[2], o[3]);
            *(float4*)(io + (size_t)node * 128 + feat + 4) = make_float4(o[4], o[5], o[6], o[7]);
        }
    }
}

// ------------------------- driver ----------------------------------------
extern "C" void kernel_launch(void* const* d_in, const int* in_sizes, int n_in,
                              void* d_out, int out_size)
{
    const float* x        = (const float*)d_in[0];
    const int*   ei       = (const int*)  d_in[1];
    const float* W1_src   = (const float*)d_in[2];
    const float* W1_dst   = (const float*)d_in[3];
    const float* att1_src = (const float*)d_in[4];
    const float* att1_dst = (const float*)d_in[5];
    const float* b1       = (const float*)d_in[6];
    const float* Wl1      = (const float*)d_in[7];
    const float* bl1      = (const float*)d_in[8];
    const float* gamma    = (const float*)d_in[9];
    const float* beta     = (const float*)d_in[10];
    const float* W2_src   = (const float*)d_in[11];
    const float* W2_dst   = (const float*)d_in[12];
    const float* att2_src = (const float*)d_in[13];
    const float* att2_dst = (const float*)d_in[14];
    const float* b2       = (const float*)d_in[15];
    const float* Wl2      = (const float*)d_in[16];
    const float* bl2      = (const float*)d_in[17];
    float* out = (float*)d_out;

    const int n = NN;
    const int E = EE;
    const int* src = ei;
    const int* dst = ei + E;

    void* p;
    cudaGetSymbolAddress(&p, g_acc1);  float* acc1 = (float*)p;
    cudaGetSymbolAddress(&p, g_h);     float* hbuf = (float*)p;
    cudaGetSymbolAddress(&p, g_Wp);    __half2* wp = (__half2*)p;
    cudaGetSymbolAddress(&p, g_biasA); float* bias = (float*)p;
    cudaGetSymbolAddress(&p, g_Vsd);   float* vsd  = (float*)p;
    void* cntp;
    cudaGetSymbolAddress(&cntp, g_cnt);

    dim3 gemm_grid((n + 127) / 128, 2);
    int node_blocks = (n * 32 + 255) / 256;
    int edge_blocks = (E + 255) / 256;

    // ordered so gemm_h sits in the ncu capture window
    cudaMemsetAsync(cntp, 0, NN * sizeof(int));
    pack_all<<<256, 256>>>(W1_src, W1_dst, Wl1, att1_src, att1_dst, bl1, b1,
                           W2_src, W2_dst, Wl2, att2_src, att2_dst, bl2, b2);
    hist_k<<<edge_blocks, 256>>>(dst, E);
    gemm_h<<<gemm_grid, 256>>>(x, acc1, wp, bias, n);
    node_logits<<<512, 256>>>(x, vsd, n);
    scan_k<<<1, 1024>>>(E);
    scatter_k<<<edge_blocks, 256>>>(src, dst, E);

    edge_fused<true><<<node_blocks, 256>>>(acc1, gamma, beta, n);

    gemm_h<<<gemm_grid, 256>>>(hbuf, out, wp + 64 * 256, bias + 128, n);
    node_logits<<<512, 256>>>(hbuf, vsd + 1024, n);
    edge_fused<false><<<node_blocks, 256>>>(out, nullptr, nullptr, n);
}

// round 7
// speedup vs baseline: 1.1112x; 1.0591x over previous
#include <cuda_runtime.h>
#include <cuda_bf16.h>
#include <cuda_fp16.h>
#include <cstdint>

#define NN 50000
#define EE 800000
#define LRELU 0.2f
#define LN_EPS 1e-5f

// ------------------------- scratch (device globals) ----------------------
__device__ __align__(16) __half g_xs_h[(size_t)NN * 128];   // fp16 xs
__device__ float g_h[(size_t)NN * 128];                     // layer1 out
__device__ float g_acc1[(size_t)NN * 128];
__device__ float g_as[NN * 4];
__device__ float g_ad[NN * 4];
__device__ __align__(16) __half2 g_Wp[2 * 64 * 384];        // [layer][k2][384 cols]
__device__ float g_biasA[2 * 128];
// CSR
__device__ int g_cnt[NN];
__device__ int g_rowptr[NN + 1];
__device__ int g_woff[NN];
__device__ int g_csrc[EE];

// ------------------------- pack: [W_src | W_lin | W_dst] -> half2 --------
__global__ void pack_all(const float* __restrict__ W1s, const float* __restrict__ W1d,
                         const float* __restrict__ Wl1, const float* __restrict__ bl1,
                         const float* __restrict__ b1,
                         const float* __restrict__ W2s, const float* __restrict__ W2d,
                         const float* __restrict__ Wl2, const float* __restrict__ bl2,
                         const float* __restrict__ b2)
{
    int i = blockIdx.x * blockDim.x + threadIdx.x;   // 96*256 = 24576 threads
    if (i < 24576) {
        int k2 = i / 384, c = i % 384;
        int k = k2 * 2;
        const float* s1;
        const float* s2;
        if (c < 128)      { s1 = W1s + c;       s2 = W2s + c; }
        else if (c < 256) { s1 = Wl1 + (c-128); s2 = Wl2 + (c-128); }
        else              { s1 = W1d + (c-256); s2 = W2d + (c-256); }
        g_Wp[(size_t)k2 * 384 + c] =
            __floats2half2_rn(s1[k * 128], s1[(k + 1) * 128]);
        g_Wp[(size_t)(64 + k2) * 384 + c] =
            __floats2half2_rn(s2[k * 128], s2[(k + 1) * 128]);
    }
    if (i < 128) {
        g_biasA[i]       = bl1[i] + b1[i];
        g_biasA[128 + i] = bl2[i] + b2[i];
    }
}

// ------------------------- CSR build -------------------------------------
__global__ void hist_k(const int* __restrict__ dst, int E)
{
    int e = blockIdx.x * blockDim.x + threadIdx.x;
    if (e < E) atomicAdd(&g_cnt[dst[e]], 1);
}

__global__ void scan_k(int E)
{
    __shared__ int ssum[1024];
    const int t = threadIdx.x;
    const int CH = (NN + 1023) / 1024;
    int base = t * CH;
    int s = 0;
    for (int i = 0; i < CH; i++) {
        int idx = base + i;
        if (idx < NN) s += g_cnt[idx];
    }
    ssum[t] = s;
    __syncthreads();
    for (int off = 1; off < 1024; off <<= 1) {
        int v = (t >= off) ? ssum[t - off] : 0;
        __syncthreads();
        ssum[t] += v;
        __syncthreads();
    }
    int run = ssum[t] - s;
    for (int i = 0; i < CH; i++) {
        int idx = base + i;
        if (idx < NN) {
            g_rowptr[idx] = run;
            g_woff[idx] = run;
            run += g_cnt[idx];
        }
    }
    if (t == 1023) g_rowptr[NN] = E;
}

__global__ void scatter_k(const int* __restrict__ src, const int* __restrict__ dst, int E)
{
    int e = blockIdx.x * blockDim.x + threadIdx.x;
    if (e >= E) return;
    int d = dst[e];
    int p = atomicAdd(&g_woff[d], 1);
    g_csrc[p] = src[e];
}

// ------------------------- fp16 tensor GEMM, 3 slices --------------------
// y==0: xs cols -> fp16 g_xs_h + a_s (fragment att-dot) -> g_as
// y==1: lin cols + bias -> fp32 acc
// y==2: xd cols -> a_d (fragment att-dot) -> g_ad; xd discarded
__global__ __launch_bounds__(256) void gemm_h(const float* __restrict__ A,
                                              float* __restrict__ acc,
                                              const __half2* __restrict__ Wp,
                                              const float* __restrict__ biasv,
                                              const float* __restrict__ att_s,
                                              const float* __restrict__ att_d,
                                              int M)
{
    __shared__ __half2 As2[128][36];
    __shared__ __half2 Bs2[32][136];

    const int tid = threadIdx.x;
    const int lane = tid & 31;
    const int warp = tid >> 5;
    const int wm = warp >> 2;
    const int wn = warp & 3;
    const int row0 = blockIdx.x * 128;
    const int y = blockIdx.y;
    const int col0 = y * 128;
    const int g = lane >> 2;
    const int t4 = lane & 3;

    float c[4][4][4];
    #pragma unroll
    for (int i = 0; i < 4; i++)
        #pragma unroll
        for (int j = 0; j < 4; j++)
            #pragma unroll
            for (int q = 0; q < 4; q++) c[i][j][q] = 0.f;

    for (int k0 = 0; k0 < 128; k0 += 64) {
        {
            int ar = tid >> 1;
            int ah = tid & 1;
            int grow = row0 + ar;
            #pragma unroll
            for (int j = 0; j < 8; j++) {
                float4 v = make_float4(0.f, 0.f, 0.f, 0.f);
                if (grow < M)
                    v = *(const float4*)(A + (size_t)grow * 128 + k0 + ah * 32 + j * 4);
                As2[ar][ah * 16 + j * 2]     = __floats2half2_rn(v.x, v.y);
                As2[ar][ah * 16 + j * 2 + 1] = __floats2half2_rn(v.z, v.w);
            }
        }
        {
            int k2r = tid >> 3;
            int colg = (tid & 7) * 16;
            const uint4* srcp = (const uint4*)(Wp + (size_t)(k0 / 2 + k2r) * 384 + col0 + colg);
            #pragma unroll
            for (int q = 0; q < 4; q++)
                *(uint4*)&Bs2[k2r][colg + q * 4] = srcp[q];
        }
        __syncthreads();

        #pragma unroll
        for (int kk = 0; kk < 4; kk++) {
            uint32_t af[4][4], bf[4][2];
            #pragma unroll
            for (int mt = 0; mt < 4; mt++) {
                int r = wm * 64 + mt * 16 + g;
                af[mt][0] = *(const uint32_t*)&As2[r][kk * 8 + t4];
                af[mt][1] = *(const uint32_t*)&As2[r + 8][kk * 8 + t4];
                af[mt][2] = *(const uint32_t*)&As2[r][kk * 8 + 4 + t4];
                af[mt][3] = *(const uint32_t*)&As2[r + 8][kk * 8 + 4 + t4];
            }
            #pragma unroll
            for (int nt = 0; nt < 4; nt++) {
                int cc = wn * 32 + nt * 8 + g;
                bf[nt][0] = *(const uint32_t*)&Bs2[kk * 8 + t4][cc];
                bf[nt][1] = *(const uint32_t*)&Bs2[kk * 8 + 4 + t4][cc];
            }
            #pragma unroll
            for (int mt = 0; mt < 4; mt++)
                #pragma unroll
                for (int nt = 0; nt < 4; nt++) {
                    asm volatile(
                        "mma.sync.aligned.m16n8k16.row.col.f32.f16.f16.f32 "
                        "{%0,%1,%2,%3}, {%4,%5,%6,%7}, {%8,%9}, {%0,%1,%2,%3};"
                        : "+f"(c[mt][nt][0]), "+f"(c[mt][nt][1]),
                          "+f"(c[mt][nt][2]), "+f"(c[mt][nt][3])
                        : "r"(af[mt][0]), "r"(af[mt][1]), "r"(af[mt][2]), "r"(af[mt][3]),
                          "r"(bf[nt][0]), "r"(bf[nt][1]));
                }
        }
        __syncthreads();
    }

    const int l2 = t4 * 2;
    if (y == 1) {
        #pragma unroll
        for (int mt = 0; mt < 4; mt++) {
            #pragma unroll
            for (int nt = 0; nt < 4; nt++) {
                int r = row0 + wm * 64 + mt * 16 + g;
                int cc = wn * 32 + nt * 8 + l2;
                float2 b2 = *(const float2*)(biasv + cc);
                float2 v01 = make_float2(c[mt][nt][0] + b2.x, c[mt][nt][1] + b2.y);
                float2 v23 = make_float2(c[mt][nt][2] + b2.x, c[mt][nt][3] + b2.y);
                if (r < M)     *(float2*)(acc + (size_t)r * 128 + cc) = v01;
                if (r + 8 < M) *(float2*)(acc + (size_t)(r + 8) * 128 + cc) = v23;
            }
        }
    } else {
        // att-dot in registers: head == wn (C=32 aligns with the warp col tile)
        const float* att = (y == 0) ? att_s : att_d;
        float* adst = (y == 0) ? g_as : g_ad;
        float2 attv[4];
        #pragma unroll
        for (int nt = 0; nt < 4; nt++)
            attv[nt] = *(const float2*)(att + wn * 32 + nt * 8 + l2);

        #pragma unroll
        for (int mt = 0; mt < 4; mt++) {
            int r = row0 + wm * 64 + mt * 16 + g;
            float p0 = 0.f, p1 = 0.f;
            #pragma unroll
            for (int nt = 0; nt < 4; nt++) {
                p0 = fmaf(c[mt][nt][0], attv[nt].x, fmaf(c[mt][nt][1], attv[nt].y, p0));
                p1 = fmaf(c[mt][nt][2], attv[nt].x, fmaf(c[mt][nt][3], attv[nt].y, p1));
                if (y == 0) {
                    int cc = wn * 32 + nt * 8 + l2;
                    if (r < M)
                        *(half2*)(g_xs_h + (size_t)r * 128 + cc) =
                            __floats2half2_rn(c[mt][nt][0], c[mt][nt][1]);
                    if (r + 8 < M)
                        *(half2*)(g_xs_h + (size_t)(r + 8) * 128 + cc) =
                            __floats2half2_rn(c[mt][nt][2], c[mt][nt][3]);
                }
            }
            p0 += __shfl_xor_sync(0xFFFFFFFFu, p0, 1);
            p0 += __shfl_xor_sync(0xFFFFFFFFu, p0, 2);
            p1 += __shfl_xor_sync(0xFFFFFFFFu, p1, 1);
            p1 += __shfl_xor_sync(0xFFFFFFFFu, p1, 2);
            if ((lane & 3) == 0) {
                if (r < M)     adst[r * 4 + wn] = p0;
                if (r + 8 < M) adst[(r + 8) * 4 + wn] = p1;
            }
        }
    }
}

// ------------------------- fast exp (FMA pipe) ---------------------------
__device__ __forceinline__ float fast_exp(float x)
{
    float t  = fmaf(x, 1.4426950408889634f, 12582912.0f);
    int   i  = __float_as_int(t);
    float fi = t - 12582912.0f;
    float f  = fmaf(x, 1.4426950408889634f, -fi);
    float p  = 0.0013333558f;
    p = fmaf(p, f, 0.0096181291f);
    p = fmaf(p, f, 0.0555041087f);
    p = fmaf(p, f, 0.2402265070f);
    p = fmaf(p, f, 0.6931471806f);
    p = fmaf(p, f, 1.0f);
    return __int_as_float(__float_as_int(p) + (i << 23));
}

// ------------------------- fused edge softmax-SpMM (+LN) -----------------
template <bool DO_LN>
__global__ __launch_bounds__(256) void edge_fused(float* __restrict__ io,
                                                  const float* __restrict__ gamma,
                                                  const float* __restrict__ beta,
                                                  int n)
{
    __shared__ float4 s_w4[8][32];
    const int wid = threadIdx.x >> 5;
    const int lane = threadIdx.x & 31;
    int node = (blockIdx.x * blockDim.x + threadIdx.x) >> 5;
    if (node >= n) return;

    const int rs = g_rowptr[node], re = g_rowptr[node + 1];
    const float4 ad4 = *(const float4*)(g_ad + (size_t)node * 4);
    const int hh = (lane & 15) >> 2;
    const int feat = (lane & 15) * 8;

    float acc[8] = {0.f, 0.f, 0.f, 0.f, 0.f, 0.f, 0.f, 0.f};
    float4 den = make_float4(0.f, 0.f, 0.f, 0.f);

    for (int base = rs; base < re; base += 32) {
        int e = base + lane;
        int sreg = 0;
        float4 w4 = make_float4(0.f, 0.f, 0.f, 0.f);
        if (e < re) {
            sreg = g_csrc[e];
            float4 a = *(const float4*)(g_as + (size_t)sreg * 4);
            float vx = a.x + ad4.x, vy = a.y + ad4.y;
            float vz = a.z + ad4.z, vw = a.w + ad4.w;
            vx = vx > 0.f ? vx : LRELU * vx;
            vy = vy > 0.f ? vy : LRELU * vy;
            vz = vz > 0.f ? vz : LRELU * vz;
            vw = vw > 0.f ? vw : LRELU * vw;
            w4.x = fast_exp(vx); w4.y = fast_exp(vy);
            w4.z = fast_exp(vz); w4.w = fast_exp(vw);
        }
        float4 t = w4;
        #pragma unroll
        for (int m = 16; m >= 1; m >>= 1) {
            t.x += __shfl_xor_sync(0xFFFFFFFFu, t.x, m);
            t.y += __shfl_xor_sync(0xFFFFFFFFu, t.y, m);
            t.z += __shfl_xor_sync(0xFFFFFFFFu, t.z, m);
            t.w += __shfl_xor_sync(0xFFFFFFFFu, t.w, m);
        }
        den.x += t.x; den.y += t.y; den.z += t.z; den.w += t.w;
        s_w4[wid][lane] = w4;
        __syncwarp();

        int cnt = min(32, re - base);
        int iters = (cnt + 1) >> 1;
        #pragma unroll 4
        for (int it = 0; it < iters; it++) {
            int jsel = 2 * it + (lane >> 4);
            int sj = __shfl_sync(0xFFFFFFFFu, sreg, jsel);
            float wv = ((const float*)&s_w4[wid][jsel])[hh];
            uint4 raw = *(const uint4*)(g_xs_h + (size_t)sj * 128 + feat);
            float2 f0 = __half22float2(*(half2*)&raw.x);
            float2 f1 = __half22float2(*(half2*)&raw.y);
            float2 f2 = __half22float2(*(half2*)&raw.z);
            float2 f3 = __half22float2(*(half2*)&raw.w);
            acc[0] = fmaf(wv, f0.x, acc[0]); acc[1] = fmaf(wv, f0.y, acc[1]);
            acc[2] = fmaf(wv, f1.x, acc[2]); acc[3] = fmaf(wv, f1.y, acc[3]);
            acc[4] = fmaf(wv, f2.x, acc[4]); acc[5] = fmaf(wv, f2.y, acc[5]);
            acc[6] = fmaf(wv, f3.x, acc[6]); acc[7] = fmaf(wv, f3.y, acc[7]);
        }
        __syncwarp();
    }

    #pragma unroll
    for (int k = 0; k < 8; k++)
        acc[k] += __shfl_xor_sync(0xFFFFFFFFu, acc[k], 16);

    float dh = (hh < 2) ? (hh == 0 ? den.x : den.y) : (hh == 2 ? den.z : den.w);
    float inv = __fdividef(1.f, dh + 1e-16f);

    float4 i0 = *(const float4*)(io + (size_t)node * 128 + feat);
    float4 i1 = *(const float4*)(io + (size_t)node * 128 + feat + 4);
    float o[8];
    o[0] = fmaf(acc[0], inv, i0.x); o[1] = fmaf(acc[1], inv, i0.y);
    o[2] = fmaf(acc[2], inv, i0.z); o[3] = fmaf(acc[3], inv, i0.w);
    o[4] = fmaf(acc[4], inv, i1.x); o[5] = fmaf(acc[5], inv, i1.y);
    o[6] = fmaf(acc[6], inv, i1.z); o[7] = fmaf(acc[7], inv, i1.w);

    if (DO_LN) {
        float sum = 0.f, sq = 0.f;
        #pragma unroll
        for (int k = 0; k < 8; k++) { sum += o[k]; sq = fmaf(o[k], o[k], sq); }
        #pragma unroll
        for (int m = 1; m <= 16; m <<= 1) {
            sum += __shfl_xor_sync(0xFFFFFFFFu, sum, m);
            sq  += __shfl_xor_sync(0xFFFFFFFFu, sq, m);
        }
        float mean = sum * (1.f / 256.f);
        float var  = sq * (1.f / 256.f) - mean * mean;
        float rstd = rsqrtf(var + LN_EPS);
        float4 ga = *(const float4*)(gamma + feat);
        float4 gb = *(const float4*)(gamma + feat + 4);
        float4 ba = *(const float4*)(beta + feat);
        float4 bb = *(const float4*)(beta + feat + 4);
        float r[8];
        r[0] = fmaxf(0.f, (o[0] - mean) * rstd * ga.x + ba.x);
        r[1] = fmaxf(0.f, (o[1] - mean) * rstd * ga.y + ba.y);
        r[2] = fmaxf(0.f, (o[2] - mean) * rstd * ga.z + ba.z);
        r[3] = fmaxf(0.f, (o[3] - mean) * rstd * ga.w + ba.w);
        r[4] = fmaxf(0.f, (o[4] - mean) * rstd * gb.x + bb.x);
        r[5] = fmaxf(0.f, (o[5] - mean) * rstd * gb.y + bb.y);
        r[6] = fmaxf(0.f, (o[6] - mean) * rstd * gb.z + bb.z);
        r[7] = fmaxf(0.f, (o[7] - mean) * rstd * gb.w + bb.w);
        if (lane < 16) {
            *(float4*)(g_h + (size_t)node * 128 + feat)     = make_float4(r[0], r[1], r[2], r[3]);
            *(float4*)(g_h + (size_t)node * 128 + feat + 4) = make_float4(r[4], r[5], r[6], r[7]);
        }
    } else {
        if (lane < 16) {
            *(float4*)(io + (size_t)node * 128 + feat)     = make_float4(o[0], o[1], o[2], o[3]);
            *(float4*)(io + (size_t)node * 128 + feat + 4) = make_float4(o[4], o[5], o[6], o[7]);
        }
    }
}

// ------------------------- driver ----------------------------------------
extern "C" void kernel_launch(void* const* d_in, const int* in_sizes, int n_in,
                              void* d_out, int out_size)
{
    const float* x        = (const float*)d_in[0];
    const int*   ei       = (const int*)  d_in[1];
    const float* W1_src   = (const float*)d_in[2];
    const float* W1_dst   = (const float*)d_in[3];
    const float* att1_src = (const float*)d_in[4];
    const float* att1_dst = (const float*)d_in[5];
    const float* b1       = (const float*)d_in[6];
    const float* Wl1      = (const float*)d_in[7];
    const float* bl1      = (const float*)d_in[8];
    const float* gamma    = (const float*)d_in[9];
    const float* beta     = (const float*)d_in[10];
    const float* W2_src   = (const float*)d_in[11];
    const float* W2_dst   = (const float*)d_in[12];
    const float* att2_src = (const float*)d_in[13];
    const float* att2_dst = (const float*)d_in[14];
    const float* b2       = (const float*)d_in[15];
    const float* Wl2      = (const float*)d_in[16];
    const float* bl2      = (const float*)d_in[17];
    float* out = (float*)d_out;

    const int n = NN;
    const int E = EE;
    const int* src = ei;
    const int* dst = ei + E;

    void* p;
    cudaGetSymbolAddress(&p, g_acc1);  float* acc1 = (float*)p;
    cudaGetSymbolAddress(&p, g_h);     float* hbuf = (float*)p;
    cudaGetSymbolAddress(&p, g_Wp);    __half2* wp = (__half2*)p;
    cudaGetSymbolAddress(&p, g_biasA); float* bias = (float*)p;
    void* cntp;
    cudaGetSymbolAddress(&cntp, g_cnt);

    dim3 gemm_grid((n + 127) / 128, 3);
    int node_blocks = (n * 32 + 255) / 256;
    int edge_blocks = (E + 255) / 256;

    // order: gemm_h is the 4th kernel launch (ncu capture window)
    cudaMemsetAsync(cntp, 0, NN * sizeof(int));
    pack_all<<<96, 256>>>(W1_src, W1_dst, Wl1, bl1, b1,
                          W2_src, W2_dst, Wl2, bl2, b2);
    hist_k<<<edge_blocks, 256>>>(dst, E);
    scan_k<<<1, 1024>>>(E);
    gemm_h<<<gemm_grid, 256>>>(x, acc1, wp, bias, att1_src, att1_dst, n);   // 4th
    scatter_k<<<edge_blocks, 256>>>(src, dst, E);

    edge_fused<true><<<node_blocks, 256>>>(acc1, gamma, beta, n);

    gemm_h<<<gemm_grid, 256>>>(hbuf, out, wp + 64 * 384, bias + 128,
                               att2_src, att2_dst, n);
    edge_fused<false><<<node_blocks, 256>>>(out, nullptr, nullptr, n);
}